// round 15
// baseline (speedup 1.0000x reference)
#include <cuda_runtime.h>
#include <cuda_bf16.h>
#include <cstdint>

#define BB 4
#define CC 256
#define HH 56
#define WW 56
#define HW 3136          // 56*56
#define CK 2304          // C*9
#define COT 128          // co tile
#define PXT 64           // pixel tile (3136 = 49*64)
#define NS  (9*PXT)      // 576 samples per block per channel
#define NTILE (BB*2*49)  // 392 output tiles per GEMM
#define NPB (BB*49)      // partial-stat slots per channel (196)
#define NSEG 144         // K-steps: 9 k-pos x 16 channel-chunks of 16
#define NTRI 48          // pipeline turns: 3 segs per turn

typedef unsigned long long u64;

// ---------------- packed fp32x2 helpers ----------------
__device__ __forceinline__ u64 dup2(float x) {
    unsigned u = __float_as_uint(x);
    u64 r; asm("mov.b64 %0, {%1, %1};" : "=l"(r) : "r"(u)); return r;
}
__device__ __forceinline__ void fma2(u64& d, u64 a, u64 b) {
    asm("fma.rn.f32x2 %0, %1, %2, %0;" : "+l"(d) : "l"(a), "l"(b));
}
__device__ __forceinline__ void unpack2(u64 v, float& lo, float& hi) {
    unsigned a, b;
    asm("mov.b64 {%0, %1}, %2;" : "=r"(a), "=r"(b) : "l"(v));
    lo = __uint_as_float(a); hi = __uint_as_float(b);
}
// ---------------- cp.async helpers ----------------
__device__ __forceinline__ void cp16(unsigned dst, const void* src) {
    asm volatile("cp.async.ca.shared.global [%0], [%1], 16;" :: "r"(dst), "l"(src));
}
__device__ __forceinline__ void cp_commit() { asm volatile("cp.async.commit_group;"); }
__device__ __forceinline__ void cp_wait0()  { asm volatile("cp.async.wait_group 0;"); }

// ---------------- mma.sync / ldmatrix helpers ----------------
__device__ __forceinline__ unsigned smem_u32(const void* p) {
    unsigned a;
    asm("{ .reg .u64 t; cvta.to.shared.u64 t, %1; cvt.u32.u64 %0, t; }" : "=r"(a) : "l"(p));
    return a;
}
__device__ __forceinline__ void ldsm4(uint32_t* r, unsigned a) {
    asm volatile("ldmatrix.sync.aligned.m8n8.x4.shared.b16 {%0,%1,%2,%3}, [%4];"
                 : "=r"(r[0]), "=r"(r[1]), "=r"(r[2]), "=r"(r[3]) : "r"(a));
}
__device__ __forceinline__ void ldsm4t(uint32_t* r, unsigned a) {
    asm volatile("ldmatrix.sync.aligned.m8n8.x4.trans.shared.b16 {%0,%1,%2,%3}, [%4];"
                 : "=r"(r[0]), "=r"(r[1]), "=r"(r[2]), "=r"(r[3]) : "r"(a));
}
__device__ __forceinline__ void mma_bf(float* d, const uint32_t* a, uint32_t b0, uint32_t b1) {
    asm volatile(
        "mma.sync.aligned.m16n8k16.row.col.f32.bf16.bf16.f32 "
        "{%0,%1,%2,%3}, {%4,%5,%6,%7}, {%8,%9}, {%0,%1,%2,%3};"
        : "+f"(d[0]), "+f"(d[1]), "+f"(d[2]), "+f"(d[3])
        : "r"(a[0]), "r"(a[1]), "r"(a[2]), "r"(a[3]), "r"(b0), "r"(b1));
}
__device__ __forceinline__ uint32_t bf16x2_rn(float hi_src, float lo_src) {
    uint32_t r;
    asm("cvt.rn.bf16x2.f32 %0, %1, %2;" : "=r"(r) : "f"(hi_src), "f"(lo_src));
    return r;
}
#define SWZ(o)  ((o) ^ (((o) >> 3) & 0x70))          // SW128 for 128B rows
#define ASWZ(o) ((o) ^ (((o) & 0x80) >> 3))          // conflict-free for 32B rows

// ---------------- scratch (static device memory) ----------------
__device__ float g_offp[4][BB*18*HW];  // offset conv partials (C-quarters)
__device__ float g_t1 [BB*CC*HW];      // deform conv output (pre-BN)
__device__ float g_t3 [BB*CC*HW];      // conv2 output (pre-BN)
__device__ __align__(16) __nv_bfloat16 g_w1bh[NSEG*CC*16];  // w1 bf16 hi: [seg][co][ci]
__device__ __align__(16) __nv_bfloat16 g_w1bl[NSEG*CC*16];  // w1 bf16 lo
__device__ __align__(16) __nv_bfloat16 g_w2bh[NSEG*CC*16];  // w2 bf16 hi
__device__ __align__(16) __nv_bfloat16 g_w2bl[NSEG*CC*16];  // w2 bf16 lo
__device__ float g_s1[CC], g_h1[CC];   // bn1 scale/shift
__device__ float g_s2[CC], g_h2[CC];   // bn2 scale/shift
__device__ float g_p1s[NPB*CC], g_p1q[NPB*CC];   // per-tile bn1 partials
__device__ float g_p2s[NPB*CC], g_p2q[NPB*CC];   // per-tile bn2 partials

// ---------------- prep: bf16 split of w1/w2 ----------------
__global__ void prep_w(const float* __restrict__ w1, const float* __restrict__ w2) {
    int i = blockIdx.x * blockDim.x + threadIdx.x;
    if (i < CK*CC) {
        int co = i / CK, r = i % CK;
        int c = r / 9, k = r % 9;
        int seg = k*16 + (c >> 4), ci = c & 15;
        size_t o = ((size_t)seg*CC + co)*16 + ci;

        float v = w1[i];
        unsigned vb = __float_as_uint(v);
        g_w1bh[o] = __ushort_as_bfloat16((unsigned short)(vb >> 16));
        g_w1bl[o] = __float2bfloat16_rn(v - __uint_as_float(vb & 0xFFFF0000u));

        v = w2[i];
        vb = __float_as_uint(v);
        g_w2bh[o] = __ushort_as_bfloat16((unsigned short)(vb >> 16));
        g_w2bl[o] = __float2bfloat16_rn(v - __uint_as_float(vb & 0xFFFF0000u));
    }
}

// ---------------- offset conv (unchanged) ----------------
__global__ void __launch_bounds__(224) offset_conv(const float* __restrict__ x,
                                                   const float* __restrict__ w_off) {
    int b = blockIdx.z, q = blockIdx.y;
    int p = blockIdx.x * 224 + threadIdx.x;
    int h = p / WW, w = p % WW;
    __shared__ float w_sm[9][20];
    u64 acc[9];
#pragma unroll
    for (int m = 0; m < 9; m++) acc[m] = 0ull;

    const float* xb = x + ((size_t)(b*CC + q*64)) * HW;
    for (int c = 0; c < 64; c++) {
        __syncthreads();
        if (threadIdx.x < 162) {
            int co = threadIdx.x / 9, kk = threadIdx.x % 9;
            w_sm[kk][co] = w_off[co*CK + (q*64 + c)*9 + kk];
        }
        __syncthreads();
        float sv[9];
        const float* xp = xb + c*HW;
#pragma unroll
        for (int k = 0; k < 9; k++) {
            int yy = h + (k/3)*2 - 2;
            int xx = w + (k%3)*2 - 2;
            sv[k] = ((unsigned)yy < HH && (unsigned)xx < WW) ? xp[yy*WW + xx] : 0.f;
        }
#pragma unroll
        for (int k = 0; k < 9; k++) {
            u64 s2 = dup2(sv[k]);
            const u64* wp = (const u64*)&w_sm[k][0];
#pragma unroll
            for (int m = 0; m < 9; m++) fma2(acc[m], wp[m], s2);
        }
    }
#pragma unroll
    for (int m = 0; m < 9; m++) {
        float lo, hi; unpack2(acc[m], lo, hi);
        g_offp[q][(size_t)(b*18 + 2*m    )*HW + p] = lo;
        g_offp[q][(size_t)(b*18 + 2*m + 1)*HW + p] = hi;
    }
}

// ---------------- shared layouts (dynamic smem; >48KB) ----------------
struct DS3 {   // deform: 90 KB
    int   ix[4][NS];
    float bw[4][NS];
    __align__(16) unsigned char Abuf[2][3][2][4096];   // [stage][sub][half]
    __align__(16) unsigned char Bbuf[2][3][2][2048];
};
struct C2S3 {  // conv2: 92 KB
    float s1[CC], h1[CC];
    int   ix[NS];
    float vd[NS];
    __align__(16) unsigned char Abuf[2][3][2][4096];
    __align__(16) unsigned char Bbuf[2][3][2][2048];
};

// ---------------- deformable conv: 3-seg/turn mma.sync bf16 2-split GEMM ----------------
// 392 CTAs, 256 threads, 48 pipeline turns of 3x16 channels.
// Bilinear combine happens in fetch (wv live = 12 regs); overlap is cross-warp TLP.
__global__ void __launch_bounds__(256, 2) deform_mma(const float* __restrict__ x,
                                                     const float* __restrict__ b_off) {
    extern __shared__ char smraw[];
    DS3& s = *(DS3*)smraw;
    const int tid = threadIdx.x, wid = tid >> 5, lid = tid & 31;
    const int t  = blockIdx.x;
    const int pt = t >> 1, coi = t & 1;
    const int b  = pt / 49, pbi = pt % 49;
    const int cob = coi * COT, pb = pbi * PXT;

    // meta: bilinear corner indices + masked weights, once per tile
    for (int i = tid; i < NS; i += 256) {
        int k = i / PXT, j = i % PXT;
        int p = pb + j, h = p / WW, w = p % WW;
        size_t o = (size_t)(b*18 + 2*k)*HW + p;
        float dy = g_offp[0][o] + g_offp[1][o] + g_offp[2][o] + g_offp[3][o] + b_off[2*k];
        o += HW;
        float dx = g_offp[0][o] + g_offp[1][o] + g_offp[2][o] + g_offp[3][o] + b_off[2*k + 1];
        float py = (float)(h + (k/3)*2 - 2) + dy;
        float px = (float)(w + (k%3)*2 - 2) + dx;
        float y0f = floorf(py), x0f = floorf(px);
        float wy = py - y0f, wx = px - x0f;
        int yi = (int)y0f, xi = (int)x0f;
        float vy0 = ((unsigned)yi      < HH) ? 1.f : 0.f;
        float vy1 = ((unsigned)(yi+1)  < HH) ? 1.f : 0.f;
        float vx0 = ((unsigned)xi      < WW) ? 1.f : 0.f;
        float vx1 = ((unsigned)(xi+1)  < WW) ? 1.f : 0.f;
        int cy0 = min(max(yi,   0), HH-1), cy1 = min(max(yi+1, 0), HH-1);
        int cx0 = min(max(xi,   0), WW-1), cx1 = min(max(xi+1, 0), WW-1);
        s.ix[0][i] = cy0*WW + cx0;  s.ix[1][i] = cy0*WW + cx1;
        s.ix[2][i] = cy1*WW + cx0;  s.ix[3][i] = cy1*WW + cx1;
        s.bw[0][i] = (1.f-wy)*(1.f-wx)*vy0*vx0;
        s.bw[1][i] = (1.f-wy)*wx      *vy0*vx1;
        s.bw[2][i] = wy*(1.f-wx)      *vy1*vx0;
        s.bw[3][i] = wy*wx            *vy1*vx1;
    }
    __syncthreads();

    const unsigned uA = smem_u32(&s.Abuf[0][0][0][0]);
    const unsigned uB = smem_u32(&s.Bbuf[0][0][0][0]);
    const int cl  = tid >> 4;
    const int pxg = (tid & 15) * 4;
    const unsigned bswz = SWZ((unsigned)(cl*128 + pxg*2));
    const int aco = tid >> 1, ahalf = tid & 1;
    const unsigned adst = ASWZ((unsigned)(aco*32 + ahalf*16));
    const unsigned aoff = ASWZ((unsigned)((wid*16 + (lid & 15))*32 + (lid >> 4)*16));
    unsigned boff[4];
#pragma unroll
    for (int j = 0; j < 4; j++)
        boff[j] = SWZ((unsigned)((lid & 15)*128 + (j*2 + (lid >> 4))*16));

    float acc[8][4];
#pragma unroll
    for (int j = 0; j < 8; j++)
#pragma unroll
        for (int m = 0; m < 4; m++) acc[j][m] = 0.f;

    const float* xb = x + (size_t)b*CC*HW;
    float wv[3][4];   // combined bilinear samples (combine in fetch)
    int ibr[3];

    auto stage_A3 = [&](int pr, int st) {
#pragma unroll
        for (int sub = 0; sub < 3; sub++) {
            int seg = 3*pr + sub;
            size_t so = ((size_t)seg*CC + cob + aco)*16 + ahalf*8;
            unsigned base = uA + (unsigned)(st*24576 + sub*8192);
            cp16(base         + adst, g_w1bh + so);
            cp16(base + 4096u + adst, g_w1bl + so);
        }
        cp_commit();
    };
    auto fetch3 = [&](int pr) {
#pragma unroll
        for (int sub = 0; sub < 3; sub++) {
            int seg = 3*pr + sub;
            int k = seg >> 4, cb = seg & 15;
            int c = cb*16 + cl;
            ibr[sub] = k*PXT + pxg;
            const float* xp = xb + (size_t)c*HW;
#pragma unroll
            for (int j = 0; j < 4; j++) {
                int i = ibr[sub] + j;
                float v0 = __ldg(xp + s.ix[0][i]);
                float v1 = __ldg(xp + s.ix[1][i]);
                float v2 = __ldg(xp + s.ix[2][i]);
                float v3 = __ldg(xp + s.ix[3][i]);
                wv[sub][j] = v0*s.bw[0][i] + v1*s.bw[1][i]
                           + v2*s.bw[2][i] + v3*s.bw[3][i];
            }
        }
    };
    auto store_B3 = [&](int st) {
#pragma unroll
        for (int sub = 0; sub < 3; sub++) {
            unsigned b0 = __float_as_uint(wv[sub][0]), b1 = __float_as_uint(wv[sub][1]);
            unsigned b2 = __float_as_uint(wv[sub][2]), b3 = __float_as_uint(wv[sub][3]);
            unsigned hA = __byte_perm(b0, b1, 0x7632);
            unsigned hB = __byte_perm(b2, b3, 0x7632);
            float l0 = wv[sub][0] - __uint_as_float(b0 & 0xFFFF0000u);
            float l1 = wv[sub][1] - __uint_as_float(b1 & 0xFFFF0000u);
            float l2 = wv[sub][2] - __uint_as_float(b2 & 0xFFFF0000u);
            float l3 = wv[sub][3] - __uint_as_float(b3 & 0xFFFF0000u);
            unsigned lA = bf16x2_rn(l1, l0);
            unsigned lB = bf16x2_rn(l3, l2);
            unsigned char* bh = &s.Bbuf[st][sub][0][0];
            unsigned char* bl = &s.Bbuf[st][sub][1][0];
            *(uint2*)(bh + bswz) = make_uint2(hA, hB);
            *(uint2*)(bl + bswz) = make_uint2(lA, lB);
        }
    };

    stage_A3(0, 0);
    fetch3(0);

    for (int pr = 0; pr < NTRI; pr++) {
        int st = pr & 1;
        cp_wait0();
        store_B3(st);
        __syncthreads();
        if (pr + 1 < NTRI) { stage_A3(pr + 1, st ^ 1); fetch3(pr + 1); }

#pragma unroll
        for (int sub = 0; sub < 3; sub++) {
            unsigned ab = uA + (unsigned)(st*24576 + sub*8192);
            unsigned bb = uB + (unsigned)(st*12288 + sub*4096);
            uint32_t ah[4], al[4];
            ldsm4(ah, ab         + aoff);
            ldsm4(al, ab + 4096u + aoff);
#pragma unroll
            for (int j = 0; j < 4; j++) {
                uint32_t bh[4], bl[4];
                ldsm4t(bh, bb         + boff[j]);
                ldsm4t(bl, bb + 2048u + boff[j]);
                mma_bf(acc[2*j],     ah, bh[0], bh[1]);
                mma_bf(acc[2*j],     ah, bl[0], bl[1]);
                mma_bf(acc[2*j],     al, bh[0], bh[1]);
                mma_bf(acc[2*j + 1], ah, bh[2], bh[3]);
                mma_bf(acc[2*j + 1], ah, bl[2], bl[3]);
                mma_bf(acc[2*j + 1], al, bh[2], bh[3]);
            }
        }
    }

    // epilogue: fragment rows -> g_t1 + deterministic BN1 partials
    {
        int co0 = cob + wid*16 + (lid >> 2);
        int co1 = co0 + 8;
        int pxo = (lid & 3) * 2;
        float* r0 = g_t1 + ((size_t)(b*CC + co0))*HW + pb + pxo;
        float* r1 = g_t1 + ((size_t)(b*CC + co1))*HW + pb + pxo;
        float s0 = 0.f, q0 = 0.f, s1v = 0.f, q1v = 0.f;
#pragma unroll
        for (int j = 0; j < 8; j++) {
            float v0 = acc[j][0], v1 = acc[j][1], v2 = acc[j][2], v3 = acc[j][3];
            r0[j*8]     = v0;  r0[j*8 + 1] = v1;
            r1[j*8]     = v2;  r1[j*8 + 1] = v3;
            s0 += v0 + v1;  q0 += v0*v0 + v1*v1;
            s1v += v2 + v3; q1v += v2*v2 + v3*v3;
        }
#pragma unroll
        for (int o = 1; o <= 2; o <<= 1) {
            s0  += __shfl_xor_sync(0xffffffffu, s0,  o, 4);
            q0  += __shfl_xor_sync(0xffffffffu, q0,  o, 4);
            s1v += __shfl_xor_sync(0xffffffffu, s1v, o, 4);
            q1v += __shfl_xor_sync(0xffffffffu, q1v, o, 4);
        }
        if ((lid & 3) == 0) {
            g_p1s[pt*CC + co0] = s0;   g_p1q[pt*CC + co0] = q0;
            g_p1s[pt*CC + co1] = s1v;  g_p1q[pt*CC + co1] = q1v;
        }
    }
}

// ---------------- BN finalize ----------------
__global__ void bn_finalize(int which, const float* __restrict__ gamma,
                            const float* __restrict__ beta) {
    int c = blockIdx.x, t = threadIdx.x;
    const float* ps = (which == 0) ? g_p1s : g_p2s;
    const float* pq = (which == 0) ? g_p1q : g_p2q;
    float s = 0.f, q = 0.f;
    for (int i = t; i < NPB; i += 64) { s += ps[i*CC + c]; q += pq[i*CC + c]; }
    __shared__ float as[2], aq[2];
#pragma unroll
    for (int o = 16; o; o >>= 1) {
        s += __shfl_down_sync(0xffffffffu, s, o);
        q += __shfl_down_sync(0xffffffffu, q, o);
    }
    if ((t & 31) == 0) { as[t >> 5] = s; aq[t >> 5] = q; }
    __syncthreads();
    if (t == 0) {
        s = as[0] + as[1]; q = aq[0] + aq[1];
        float n = (float)(BB*HW);
        float mean = s / n;
        float var  = q / n - mean*mean;
        float scale = gamma[c] * rsqrtf(var + 1e-5f);
        if (which == 0) { g_s1[c] = scale; g_h1[c] = beta[c] - mean*scale; }
        else            { g_s2[c] = scale; g_h2[c] = beta[c] - mean*scale; }
    }
}

// ---------------- conv2: 3-seg/turn mma.sync bf16 2-split GEMM ----------------
__global__ void __launch_bounds__(256, 2) conv2_mma() {
    extern __shared__ char smraw[];
    C2S3& s = *(C2S3*)smraw;
    const int tid = threadIdx.x, wid = tid >> 5, lid = tid & 31;
    const int t  = blockIdx.x;
    const int pt = t >> 1, coi = t & 1;
    const int b  = pt / 49, pbi = pt % 49;
    const int cob = coi * COT, pb = pbi * PXT;

    s.s1[tid] = g_s1[tid];
    s.h1[tid] = g_h1[tid];
    for (int i = tid; i < NS; i += 256) {
        int k = i / PXT, j = i % PXT;
        int p = pb + j, h = p / WW, w = p % WW;
        int y = h + k/3 - 1, xx = w + k%3 - 1;
        int ok = ((unsigned)y < HH && (unsigned)xx < WW);
        s.ix[i] = ok ? (y*WW + xx) : 0;
        s.vd[i] = ok ? 1.f : 0.f;
    }
    __syncthreads();

    const unsigned uA = smem_u32(&s.Abuf[0][0][0][0]);
    const unsigned uB = smem_u32(&s.Bbuf[0][0][0][0]);
    const int cl  = tid >> 4;
    const int pxg = (tid & 15) * 4;
    const unsigned bswz = SWZ((unsigned)(cl*128 + pxg*2));
    const int aco = tid >> 1, ahalf = tid & 1;
    const unsigned adst = ASWZ((unsigned)(aco*32 + ahalf*16));
    const unsigned aoff = ASWZ((unsigned)((wid*16 + (lid & 15))*32 + (lid >> 4)*16));
    unsigned boff[4];
#pragma unroll
    for (int j = 0; j < 4; j++)
        boff[j] = SWZ((unsigned)((lid & 15)*128 + (j*2 + (lid >> 4))*16));

    float acc[8][4];
#pragma unroll
    for (int j = 0; j < 8; j++)
#pragma unroll
        for (int m = 0; m < 4; m++) acc[j][m] = 0.f;

    const float* tb = g_t1 + (size_t)b*CC*HW;
    float pv[3][4];
    float sc_r[3], sh_r[3];
    int ibr[3];

    auto stage_A3 = [&](int pr, int st) {
#pragma unroll
        for (int sub = 0; sub < 3; sub++) {
            int seg = 3*pr + sub;
            size_t so = ((size_t)seg*CC + cob + aco)*16 + ahalf*8;
            unsigned base = uA + (unsigned)(st*24576 + sub*8192);
            cp16(base         + adst, g_w2bh + so);
            cp16(base + 4096u + adst, g_w2bl + so);
        }
        cp_commit();
    };
    auto fetch3 = [&](int pr) {
#pragma unroll
        for (int sub = 0; sub < 3; sub++) {
            int seg = 3*pr + sub;
            int k = seg >> 4, cb = seg & 15;
            int c = cb*16 + cl;
            ibr[sub] = k*PXT + pxg;
            sc_r[sub] = s.s1[c]; sh_r[sub] = s.h1[c];
            const float* tp = tb + (size_t)c*HW;
#pragma unroll
            for (int j = 0; j < 4; j++) pv[sub][j] = __ldg(tp + s.ix[ibr[sub] + j]);
        }
    };
    auto store_B3 = [&](int st) {
#pragma unroll
        for (int sub = 0; sub < 3; sub++) {
            float w0 = fmaxf(fmaf(pv[sub][0], sc_r[sub], sh_r[sub]), 0.f) * s.vd[ibr[sub]];
            float w1 = fmaxf(fmaf(pv[sub][1], sc_r[sub], sh_r[sub]), 0.f) * s.vd[ibr[sub] + 1];
            float w2 = fmaxf(fmaf(pv[sub][2], sc_r[sub], sh_r[sub]), 0.f) * s.vd[ibr[sub] + 2];
            float w3 = fmaxf(fmaf(pv[sub][3], sc_r[sub], sh_r[sub]), 0.f) * s.vd[ibr[sub] + 3];
            unsigned b0 = __float_as_uint(w0), b1 = __float_as_uint(w1);
            unsigned b2 = __float_as_uint(w2), b3 = __float_as_uint(w3);
            unsigned hA = __byte_perm(b0, b1, 0x7632);
            unsigned hB = __byte_perm(b2, b3, 0x7632);
            float l0 = w0 - __uint_as_float(b0 & 0xFFFF0000u);
            float l1 = w1 - __uint_as_float(b1 & 0xFFFF0000u);
            float l2 = w2 - __uint_as_float(b2 & 0xFFFF0000u);
            float l3 = w3 - __uint_as_float(b3 & 0xFFFF0000u);
            unsigned lA = bf16x2_rn(l1, l0);
            unsigned lB = bf16x2_rn(l3, l2);
            unsigned char* bh = &s.Bbuf[st][sub][0][0];
            unsigned char* bl = &s.Bbuf[st][sub][1][0];
            *(uint2*)(bh + bswz) = make_uint2(hA, hB);
            *(uint2*)(bl + bswz) = make_uint2(lA, lB);
        }
    };

    stage_A3(0, 0);
    fetch3(0);

    for (int pr = 0; pr < NTRI; pr++) {
        int st = pr & 1;
        cp_wait0();
        store_B3(st);
        __syncthreads();
        if (pr + 1 < NTRI) { stage_A3(pr + 1, st ^ 1); fetch3(pr + 1); }

#pragma unroll
        for (int sub = 0; sub < 3; sub++) {
            unsigned ab = uA + (unsigned)(st*24576 + sub*8192);
            unsigned bb = uB + (unsigned)(st*12288 + sub*4096);
            uint32_t ah[4], al[4];
            ldsm4(ah, ab         + aoff);
            ldsm4(al, ab + 4096u + aoff);
#pragma unroll
            for (int j = 0; j < 4; j++) {
                uint32_t bh[4], bl[4];
                ldsm4t(bh, bb         + boff[j]);
                ldsm4t(bl, bb + 2048u + boff[j]);
                mma_bf(acc[2*j],     ah, bh[0], bh[1]);
                mma_bf(acc[2*j],     ah, bl[0], bl[1]);
                mma_bf(acc[2*j],     al, bh[0], bh[1]);
                mma_bf(acc[2*j + 1], ah, bh[2], bh[3]);
                mma_bf(acc[2*j + 1], ah, bl[2], bl[3]);
                mma_bf(acc[2*j + 1], al, bh[2], bh[3]);
            }
        }
    }

    {
        int co0 = cob + wid*16 + (lid >> 2);
        int co1 = co0 + 8;
        int pxo = (lid & 3) * 2;
        float* r0 = g_t3 + ((size_t)(b*CC + co0))*HW + pb + pxo;
        float* r1 = g_t3 + ((size_t)(b*CC + co1))*HW + pb + pxo;
        float s0 = 0.f, q0 = 0.f, s1v = 0.f, q1v = 0.f;
#pragma unroll
        for (int j = 0; j < 8; j++) {
            float v0 = acc[j][0], v1 = acc[j][1], v2 = acc[j][2], v3 = acc[j][3];
            r0[j*8]     = v0;  r0[j*8 + 1] = v1;
            r1[j*8]     = v2;  r1[j*8 + 1] = v3;
            s0 += v0 + v1;  q0 += v0*v0 + v1*v1;
            s1v += v2 + v3; q1v += v2*v2 + v3*v3;
        }
#pragma unroll
        for (int o = 1; o <= 2; o <<= 1) {
            s0  += __shfl_xor_sync(0xffffffffu, s0,  o, 4);
            q0  += __shfl_xor_sync(0xffffffffu, q0,  o, 4);
            s1v += __shfl_xor_sync(0xffffffffu, s1v, o, 4);
            q1v += __shfl_xor_sync(0xffffffffu, q1v, o, 4);
        }
        if ((lid & 3) == 0) {
            g_p2s[pt*CC + co0] = s0;   g_p2q[pt*CC + co0] = q0;
            g_p2s[pt*CC + co1] = s1v;  g_p2q[pt*CC + co1] = q1v;
        }
    }
}

// ---------------- epilogue: out = relu(bn2(t3) + x), float4 ----------------
__global__ void epilogue(const float* __restrict__ x, float* __restrict__ out) {
    int i4 = blockIdx.x * blockDim.x + threadIdx.x;
    if (i4 < BB*CC*HW/4) {
        int i = i4 * 4;
        int c = (i / HW) % CC;
        float sc = g_s2[c], sh = g_h2[c];
        float4 t  = *(const float4*)&g_t3[i];
        float4 xv = *(const float4*)&x[i];
        float4 o;
        o.x = fmaxf(fmaf(t.x, sc, sh) + xv.x, 0.f);
        o.y = fmaxf(fmaf(t.y, sc, sh) + xv.y, 0.f);
        o.z = fmaxf(fmaf(t.z, sc, sh) + xv.z, 0.f);
        o.w = fmaxf(fmaf(t.w, sc, sh) + xv.w, 0.f);
        *(float4*)&out[i] = o;
    }
}

// ---------------- launch ----------------
extern "C" void kernel_launch(void* const* d_in, const int* in_sizes, int n_in,
                              void* d_out, int out_size) {
    const float* x      = (const float*)d_in[0];
    const float* w_off  = (const float*)d_in[1];
    const float* b_off  = (const float*)d_in[2];
    const float* w1     = (const float*)d_in[3];
    const float* gamma1 = (const float*)d_in[4];
    const float* beta1  = (const float*)d_in[5];
    const float* w2     = (const float*)d_in[6];
    const float* gamma2 = (const float*)d_in[7];
    const float* beta2  = (const float*)d_in[8];
    float* out = (float*)d_out;

    // idempotent opt-in for >48KB dynamic smem (host API, graph-safe, no alloc)
    cudaFuncSetAttribute(deform_mma, cudaFuncAttributeMaxDynamicSharedMemorySize,
                         (int)sizeof(DS3));
    cudaFuncSetAttribute(conv2_mma, cudaFuncAttributeMaxDynamicSharedMemorySize,
                         (int)sizeof(C2S3));

    prep_w<<<(CK*CC + 255)/256, 256>>>(w1, w2);
    offset_conv<<<dim3(14, 4, BB), 224>>>(x, w_off);
    deform_mma<<<NTILE, 256, sizeof(DS3)>>>(x, b_off);
    bn_finalize<<<CC, 64>>>(0, gamma1, beta1);
    conv2_mma<<<NTILE, 256, sizeof(C2S3)>>>();
    bn_finalize<<<CC, 64>>>(1, gamma2, beta2);
    epilogue<<<(BB*CC*HW/4 + 255)/256, 256>>>(x, out);
}

// round 16
// speedup vs baseline: 1.0168x; 1.0168x over previous
#include <cuda_runtime.h>
#include <cuda_bf16.h>
#include <cstdint>

#define BB 4
#define CC 256
#define HH 56
#define WW 56
#define HW 3136          // 56*56
#define CK 2304          // C*9
#define COT 128          // co tile
#define PXT 64           // pixel tile (3136 = 49*64)
#define NS  (9*PXT)      // 576 samples per block per channel
#define NTILE (BB*2*49)  // 392 output tiles per GEMM
#define NPB (BB*49)      // partial-stat slots per channel (196)
#define NSEG 144         // K-steps: 9 k-pos x 16 channel-chunks of 16
#define NPAIR 72         // pipeline turns: 2 segs per turn
#define ONT (BB*49)      // offset GEMM tiles (196)

typedef unsigned long long u64;

// ---------------- cp.async helpers ----------------
__device__ __forceinline__ void cp16(unsigned dst, const void* src) {
    asm volatile("cp.async.ca.shared.global [%0], [%1], 16;" :: "r"(dst), "l"(src));
}
__device__ __forceinline__ void cp_commit() { asm volatile("cp.async.commit_group;"); }
__device__ __forceinline__ void cp_wait0()  { asm volatile("cp.async.wait_group 0;"); }

// ---------------- mma.sync / ldmatrix helpers ----------------
__device__ __forceinline__ unsigned smem_u32(const void* p) {
    unsigned a;
    asm("{ .reg .u64 t; cvta.to.shared.u64 t, %1; cvt.u32.u64 %0, t; }" : "=r"(a) : "l"(p));
    return a;
}
__device__ __forceinline__ void ldsm4(uint32_t* r, unsigned a) {
    asm volatile("ldmatrix.sync.aligned.m8n8.x4.shared.b16 {%0,%1,%2,%3}, [%4];"
                 : "=r"(r[0]), "=r"(r[1]), "=r"(r[2]), "=r"(r[3]) : "r"(a));
}
__device__ __forceinline__ void ldsm4t(uint32_t* r, unsigned a) {
    asm volatile("ldmatrix.sync.aligned.m8n8.x4.trans.shared.b16 {%0,%1,%2,%3}, [%4];"
                 : "=r"(r[0]), "=r"(r[1]), "=r"(r[2]), "=r"(r[3]) : "r"(a));
}
__device__ __forceinline__ void mma_bf(float* d, const uint32_t* a, uint32_t b0, uint32_t b1) {
    asm volatile(
        "mma.sync.aligned.m16n8k16.row.col.f32.bf16.bf16.f32 "
        "{%0,%1,%2,%3}, {%4,%5,%6,%7}, {%8,%9}, {%0,%1,%2,%3};"
        : "+f"(d[0]), "+f"(d[1]), "+f"(d[2]), "+f"(d[3])
        : "r"(a[0]), "r"(a[1]), "r"(a[2]), "r"(a[3]), "r"(b0), "r"(b1));
}
__device__ __forceinline__ uint32_t bf16x2_rn(float hi_src, float lo_src) {
    uint32_t r;
    asm("cvt.rn.bf16x2.f32 %0, %1, %2;" : "=r"(r) : "f"(hi_src), "f"(lo_src));
    return r;
}
#define SWZ(o)  ((o) ^ (((o) >> 3) & 0x70))          // SW128 for 128B rows
#define ASWZ(o) ((o) ^ (((o) & 0x80) >> 3))          // conflict-free for 32B rows

// ---------------- scratch (static device memory) ----------------
__device__ float g_offn[BB*18*HW];     // offset conv output (final, single writer)
__device__ float g_t1 [BB*CC*HW];      // deform conv output (pre-BN)
__device__ float g_t3 [BB*CC*HW];      // conv2 output (pre-BN)
__device__ __align__(16) __nv_bfloat16 g_w1bh[NSEG*CC*16];  // w1 bf16 hi: [seg][co][ci]
__device__ __align__(16) __nv_bfloat16 g_w1bl[NSEG*CC*16];  // w1 bf16 lo
__device__ __align__(16) __nv_bfloat16 g_w2bh[NSEG*CC*16];  // w2 bf16 hi
__device__ __align__(16) __nv_bfloat16 g_w2bl[NSEG*CC*16];  // w2 bf16 lo
__device__ __align__(16) __nv_bfloat16 g_wobh[NSEG*16*64];  // w_off bf16 hi: [seg][ci][co64pad]
__device__ __align__(16) __nv_bfloat16 g_wobl[NSEG*16*64];  // w_off bf16 lo
__device__ float g_s1[CC], g_h1[CC];   // bn1 scale/shift
__device__ float g_s2[CC], g_h2[CC];   // bn2 scale/shift
__device__ float g_p1s[NPB*CC], g_p1q[NPB*CC];   // per-tile bn1 partials
__device__ float g_p2s[NPB*CC], g_p2q[NPB*CC];   // per-tile bn2 partials

// ---------------- prep: bf16 split of w1/w2/w_off ----------------
__global__ void prep_w(const float* __restrict__ w1, const float* __restrict__ w2,
                       const float* __restrict__ w_off) {
    int i = blockIdx.x * blockDim.x + threadIdx.x;
    if (i < CK*CC) {
        int co = i / CK, r = i % CK;
        int c = r / 9, k = r % 9;
        int seg = k*16 + (c >> 4), ci = c & 15;
        size_t o = ((size_t)seg*CC + co)*16 + ci;

        float v = w1[i];
        unsigned vb = __float_as_uint(v);
        g_w1bh[o] = __ushort_as_bfloat16((unsigned short)(vb >> 16));
        g_w1bl[o] = __float2bfloat16_rn(v - __uint_as_float(vb & 0xFFFF0000u));

        v = w2[i];
        vb = __float_as_uint(v);
        g_w2bh[o] = __ushort_as_bfloat16((unsigned short)(vb >> 16));
        g_w2bl[o] = __float2bfloat16_rn(v - __uint_as_float(vb & 0xFFFF0000u));
    }
    if (i < NSEG*16*64) {
        int seg = i >> 10;           // 16*64 = 1024 slots per seg
        int ci  = (i >> 6) & 15;
        int co  = i & 63;
        int k = seg >> 4, cb = seg & 15;
        int c = cb*16 + ci;
        float v = (co < 18) ? w_off[((size_t)co*CC + c)*9 + k] : 0.f;
        unsigned vb = __float_as_uint(v);
        g_wobh[i] = __ushort_as_bfloat16((unsigned short)(vb >> 16));
        g_wobl[i] = __float2bfloat16_rn(v - __uint_as_float(vb & 0xFFFF0000u));
    }
}

// ---------------- offset conv: mma.sync bf16 2-split GEMM ----------------
// 196 CTAs, 256 threads. Tile: 64 px (M) x 32 co (N, 18 live). 72 turns of 2x16 channels.
// 8 warps = 4 px-groups x 2 co-halves. Dil=2 pad=2 halo gather as A operand.
struct OS {
    int   ix[NS];
    float vd[NS];
    __align__(16) unsigned char Abuf[2][2][2][2048];   // [stage][sub][half]: 64px x 16ci bf16
    __align__(16) unsigned char Bbuf[2][2][2][2048];   // [stage][sub][half]: 16ci x 64co bf16 (128B rows)
};

__global__ void __launch_bounds__(256) offset_mma(const float* __restrict__ x) {
    __shared__ OS s;
    const int tid = threadIdx.x, wid = tid >> 5, lid = tid & 31;
    const int t = blockIdx.x;
    const int b = t / 49, pbi = t % 49, pb = pbi * PXT;

    for (int i = tid; i < NS; i += 256) {
        int k = i >> 6, j = i & 63;
        int p = pb + j, hh = p / WW, ww = p % WW;
        int y = hh + (k/3)*2 - 2, xx = ww + (k%3)*2 - 2;
        int ok = ((unsigned)y < HH && (unsigned)xx < WW);
        s.ix[i] = ok ? (y*WW + xx) : 0;
        s.vd[i] = ok ? 1.f : 0.f;
    }
    __syncthreads();

    const unsigned uA = smem_u32(&s.Abuf[0][0][0][0]);
    const unsigned uB = smem_u32(&s.Bbuf[0][0][0][0]);
    const int apx  = tid >> 2, acig = (tid & 3) * 4;       // A build: px, 4 ci elems
    const unsigned adst = ASWZ((unsigned)(apx*32 + acig*2));
    const int bhalf = tid >> 7, bci = (tid >> 3) & 15, bch = tid & 7;  // B stage
    const unsigned bdst = SWZ((unsigned)(bci*128 + bch*16));
    const int pxg = wid >> 1, h = wid & 1;                 // warp roles
    const unsigned aoff  = ASWZ((unsigned)((pxg*16 + (lid & 15))*32 + (lid >> 4)*16));
    const unsigned boffh = SWZ((unsigned)((lid & 15)*128 + (h*2 + (lid >> 4))*16));

    float acc[2][4];
#pragma unroll
    for (int nf = 0; nf < 2; nf++)
#pragma unroll
        for (int m = 0; m < 4; m++) acc[nf][m] = 0.f;

    float gv[2][4];
    const float* xb = x + (size_t)b*CC*HW;

    auto stageB = [&](int pr, int st) {
#pragma unroll
        for (int sub = 0; sub < 2; sub++) {
            int seg = 2*pr + sub;
            const __nv_bfloat16* src = (bhalf ? g_wobl : g_wobh)
                + ((size_t)seg*16 + bci)*64 + bch*8;
            cp16(uB + (unsigned)(st*8192 + sub*4096 + bhalf*2048) + bdst, src);
        }
        cp_commit();
    };
    auto fetchA = [&](int pr) {
#pragma unroll
        for (int sub = 0; sub < 2; sub++) {
            int seg = 2*pr + sub;
            int k = seg >> 4, cb = seg & 15;
            int gi = k*PXT + apx;
            int idx = s.ix[gi];
            float vdv = s.vd[gi];
            const float* xp = xb + ((size_t)(cb*16 + acig))*HW + idx;
#pragma unroll
            for (int j = 0; j < 4; j++) gv[sub][j] = __ldg(xp + (size_t)j*HW) * vdv;
        }
    };
    auto storeA = [&](int st) {
#pragma unroll
        for (int sub = 0; sub < 2; sub++) {
            unsigned b0 = __float_as_uint(gv[sub][0]), b1 = __float_as_uint(gv[sub][1]);
            unsigned b2 = __float_as_uint(gv[sub][2]), b3 = __float_as_uint(gv[sub][3]);
            unsigned hA = __byte_perm(b0, b1, 0x7632);
            unsigned hB = __byte_perm(b2, b3, 0x7632);
            float l0 = gv[sub][0] - __uint_as_float(b0 & 0xFFFF0000u);
            float l1 = gv[sub][1] - __uint_as_float(b1 & 0xFFFF0000u);
            float l2 = gv[sub][2] - __uint_as_float(b2 & 0xFFFF0000u);
            float l3 = gv[sub][3] - __uint_as_float(b3 & 0xFFFF0000u);
            unsigned lA = bf16x2_rn(l1, l0);
            unsigned lB = bf16x2_rn(l3, l2);
            *(uint2*)(&s.Abuf[st][sub][0][0] + adst) = make_uint2(hA, hB);
            *(uint2*)(&s.Abuf[st][sub][1][0] + adst) = make_uint2(lA, lB);
        }
    };

    stageB(0, 0);
    fetchA(0);

    for (int pr = 0; pr < NPAIR; pr++) {
        int st = pr & 1;
        cp_wait0();
        storeA(st);
        __syncthreads();
        if (pr + 1 < NPAIR) { stageB(pr + 1, st ^ 1); fetchA(pr + 1); }

#pragma unroll
        for (int sub = 0; sub < 2; sub++) {
            unsigned ab = uA + (unsigned)(st*8192 + sub*4096);
            unsigned bb = uB + (unsigned)(st*8192 + sub*4096);
            uint32_t ah[4], al[4];
            ldsm4(ah, ab         + aoff);
            ldsm4(al, ab + 2048u + aoff);
            uint32_t bh[4], bl[4];
            ldsm4t(bh, bb         + boffh);
            ldsm4t(bl, bb + 2048u + boffh);
            mma_bf(acc[0], ah, bh[0], bh[1]);
            mma_bf(acc[0], ah, bl[0], bl[1]);
            mma_bf(acc[0], al, bh[0], bh[1]);
            mma_bf(acc[1], ah, bh[2], bh[3]);
            mma_bf(acc[1], ah, bl[2], bl[3]);
            mma_bf(acc[1], al, bh[2], bh[3]);
        }
    }

    // epilogue: D[px][co] -> g_offn[b][co][px], co<18 only (single writer)
    {
        int prow = pb + pxg*16 + (lid >> 2);
#pragma unroll
        for (int nf = 0; nf < 2; nf++)
#pragma unroll
            for (int m = 0; m < 4; m++) {
                int co = h*16 + nf*8 + (lid & 3)*2 + (m & 1);
                int pr2 = prow + (m >> 1)*8;
                if (co < 18)
                    g_offn[((size_t)(b*18 + co))*HW + pr2] = acc[nf][m];
            }
    }
}

// ---------------- shared layouts for the two big GEMMs (R14, 2-sub) ----------------
struct DS2 {   // deform: 67.6 KB
    int   ix[4][NS];
    float bw[4][NS];
    __align__(16) unsigned char Abuf[2][2][2][4096];   // [stage][sub][half]
    __align__(16) unsigned char Bbuf[2][2][2][2048];
};
struct C2S2 {  // conv2: 55.8 KB
    float s1[CC], h1[CC];
    int   ix[NS];
    float vd[NS];
    __align__(16) unsigned char Abuf[2][2][2][4096];
    __align__(16) unsigned char Bbuf[2][2][2][2048];
};

// ---------------- deformable conv: paired-seg mma.sync bf16 2-split GEMM (R14) ----------------
__global__ void __launch_bounds__(256, 2) deform_mma(const float* __restrict__ x,
                                                     const float* __restrict__ b_off) {
    extern __shared__ char smraw[];
    DS2& s = *(DS2*)smraw;
    const int tid = threadIdx.x, wid = tid >> 5, lid = tid & 31;
    const int t  = blockIdx.x;
    const int pt = t >> 1, coi = t & 1;
    const int b  = pt / 49, pbi = pt % 49;
    const int cob = coi * COT, pb = pbi * PXT;

    for (int i = tid; i < NS; i += 256) {
        int k = i / PXT, j = i % PXT;
        int p = pb + j, h = p / WW, w = p % WW;
        float dy = g_offn[(size_t)(b*18 + 2*k    )*HW + p] + b_off[2*k];
        float dx = g_offn[(size_t)(b*18 + 2*k + 1)*HW + p] + b_off[2*k + 1];
        float py = (float)(h + (k/3)*2 - 2) + dy;
        float px = (float)(w + (k%3)*2 - 2) + dx;
        float y0f = floorf(py), x0f = floorf(px);
        float wy = py - y0f, wx = px - x0f;
        int yi = (int)y0f, xi = (int)x0f;
        float vy0 = ((unsigned)yi      < HH) ? 1.f : 0.f;
        float vy1 = ((unsigned)(yi+1)  < HH) ? 1.f : 0.f;
        float vx0 = ((unsigned)xi      < WW) ? 1.f : 0.f;
        float vx1 = ((unsigned)(xi+1)  < WW) ? 1.f : 0.f;
        int cy0 = min(max(yi,   0), HH-1), cy1 = min(max(yi+1, 0), HH-1);
        int cx0 = min(max(xi,   0), WW-1), cx1 = min(max(xi+1, 0), WW-1);
        s.ix[0][i] = cy0*WW + cx0;  s.ix[1][i] = cy0*WW + cx1;
        s.ix[2][i] = cy1*WW + cx0;  s.ix[3][i] = cy1*WW + cx1;
        s.bw[0][i] = (1.f-wy)*(1.f-wx)*vy0*vx0;
        s.bw[1][i] = (1.f-wy)*wx      *vy0*vx1;
        s.bw[2][i] = wy*(1.f-wx)      *vy1*vx0;
        s.bw[3][i] = wy*wx            *vy1*vx1;
    }
    __syncthreads();

    const unsigned uA = smem_u32(&s.Abuf[0][0][0][0]);
    const unsigned uB = smem_u32(&s.Bbuf[0][0][0][0]);
    const int cl  = tid >> 4;
    const int pxg = (tid & 15) * 4;
    const unsigned bswz = SWZ((unsigned)(cl*128 + pxg*2));
    const int aco = tid >> 1, ahalf = tid & 1;
    const unsigned adst = ASWZ((unsigned)(aco*32 + ahalf*16));
    const unsigned aoff = ASWZ((unsigned)((wid*16 + (lid & 15))*32 + (lid >> 4)*16));
    unsigned boff[4];
#pragma unroll
    for (int j = 0; j < 4; j++)
        boff[j] = SWZ((unsigned)((lid & 15)*128 + (j*2 + (lid >> 4))*16));

    float acc[8][4];
#pragma unroll
    for (int j = 0; j < 8; j++)
#pragma unroll
        for (int m = 0; m < 4; m++) acc[j][m] = 0.f;

    const float* xb = x + (size_t)b*CC*HW;
    float pv[2][4][4];
    int ibr[2];

    auto stage_A2 = [&](int pr, int st) {
#pragma unroll
        for (int sub = 0; sub < 2; sub++) {
            int seg = 2*pr + sub;
            size_t so = ((size_t)seg*CC + cob + aco)*16 + ahalf*8;
            unsigned base = uA + (unsigned)(st*16384 + sub*8192);
            cp16(base         + adst, g_w1bh + so);
            cp16(base + 4096u + adst, g_w1bl + so);
        }
        cp_commit();
    };
    auto fetch2 = [&](int pr) {
#pragma unroll
        for (int sub = 0; sub < 2; sub++) {
            int seg = 2*pr + sub;
            int k = seg >> 4, cb = seg & 15;
            int c = cb*16 + cl;
            ibr[sub] = k*PXT + pxg;
            const float* xp = xb + (size_t)c*HW;
#pragma unroll
            for (int j = 0; j < 4; j++) {
                int i = ibr[sub] + j;
                pv[sub][j][0] = __ldg(xp + s.ix[0][i]);
                pv[sub][j][1] = __ldg(xp + s.ix[1][i]);
                pv[sub][j][2] = __ldg(xp + s.ix[2][i]);
                pv[sub][j][3] = __ldg(xp + s.ix[3][i]);
            }
        }
    };
    auto store_B2 = [&](int st) {
#pragma unroll
        for (int sub = 0; sub < 2; sub++) {
            float wv[4];
#pragma unroll
            for (int j = 0; j < 4; j++) {
                int i = ibr[sub] + j;
                wv[j] = pv[sub][j][0]*s.bw[0][i] + pv[sub][j][1]*s.bw[1][i]
                      + pv[sub][j][2]*s.bw[2][i] + pv[sub][j][3]*s.bw[3][i];
            }
            unsigned b0 = __float_as_uint(wv[0]), b1 = __float_as_uint(wv[1]);
            unsigned b2 = __float_as_uint(wv[2]), b3 = __float_as_uint(wv[3]);
            unsigned hA = __byte_perm(b0, b1, 0x7632);
            unsigned hB = __byte_perm(b2, b3, 0x7632);
            float l0 = wv[0] - __uint_as_float(b0 & 0xFFFF0000u);
            float l1 = wv[1] - __uint_as_float(b1 & 0xFFFF0000u);
            float l2 = wv[2] - __uint_as_float(b2 & 0xFFFF0000u);
            float l3 = wv[3] - __uint_as_float(b3 & 0xFFFF0000u);
            unsigned lA = bf16x2_rn(l1, l0);
            unsigned lB = bf16x2_rn(l3, l2);
            unsigned char* bh = &s.Bbuf[st][sub][0][0];
            unsigned char* bl = &s.Bbuf[st][sub][1][0];
            *(uint2*)(bh + bswz) = make_uint2(hA, hB);
            *(uint2*)(bl + bswz) = make_uint2(lA, lB);
        }
    };

    stage_A2(0, 0);
    fetch2(0);

    for (int pr = 0; pr < NPAIR; pr++) {
        int st = pr & 1;
        cp_wait0();
        store_B2(st);
        __syncthreads();
        if (pr + 1 < NPAIR) { stage_A2(pr + 1, st ^ 1); fetch2(pr + 1); }

#pragma unroll
        for (int sub = 0; sub < 2; sub++) {
            unsigned ab = uA + (unsigned)(st*16384 + sub*8192);
            unsigned bb = uB + (unsigned)(st*8192  + sub*4096);
            uint32_t ah[4], al[4];
            ldsm4(ah, ab         + aoff);
            ldsm4(al, ab + 4096u + aoff);
#pragma unroll
            for (int j = 0; j < 4; j++) {
                uint32_t bh[4], bl[4];
                ldsm4t(bh, bb         + boff[j]);
                ldsm4t(bl, bb + 2048u + boff[j]);
                mma_bf(acc[2*j],     ah, bh[0], bh[1]);
                mma_bf(acc[2*j],     ah, bl[0], bl[1]);
                mma_bf(acc[2*j],     al, bh[0], bh[1]);
                mma_bf(acc[2*j + 1], ah, bh[2], bh[3]);
                mma_bf(acc[2*j + 1], ah, bl[2], bl[3]);
                mma_bf(acc[2*j + 1], al, bh[2], bh[3]);
            }
        }
    }

    {
        int co0 = cob + wid*16 + (lid >> 2);
        int co1 = co0 + 8;
        int pxo = (lid & 3) * 2;
        float* r0 = g_t1 + ((size_t)(b*CC + co0))*HW + pb + pxo;
        float* r1 = g_t1 + ((size_t)(b*CC + co1))*HW + pb + pxo;
        float s0 = 0.f, q0 = 0.f, s1v = 0.f, q1v = 0.f;
#pragma unroll
        for (int j = 0; j < 8; j++) {
            float v0 = acc[j][0], v1 = acc[j][1], v2 = acc[j][2], v3 = acc[j][3];
            r0[j*8]     = v0;  r0[j*8 + 1] = v1;
            r1[j*8]     = v2;  r1[j*8 + 1] = v3;
            s0 += v0 + v1;  q0 += v0*v0 + v1*v1;
            s1v += v2 + v3; q1v += v2*v2 + v3*v3;
        }
#pragma unroll
        for (int o = 1; o <= 2; o <<= 1) {
            s0  += __shfl_xor_sync(0xffffffffu, s0,  o, 4);
            q0  += __shfl_xor_sync(0xffffffffu, q0,  o, 4);
            s1v += __shfl_xor_sync(0xffffffffu, s1v, o, 4);
            q1v += __shfl_xor_sync(0xffffffffu, q1v, o, 4);
        }
        if ((lid & 3) == 0) {
            g_p1s[pt*CC + co0] = s0;   g_p1q[pt*CC + co0] = q0;
            g_p1s[pt*CC + co1] = s1v;  g_p1q[pt*CC + co1] = q1v;
        }
    }
}

// ---------------- BN finalize ----------------
__global__ void bn_finalize(int which, const float* __restrict__ gamma,
                            const float* __restrict__ beta) {
    int c = blockIdx.x, t = threadIdx.x;
    const float* ps = (which == 0) ? g_p1s : g_p2s;
    const float* pq = (which == 0) ? g_p1q : g_p2q;
    float s = 0.f, q = 0.f;
    for (int i = t; i < NPB; i += 64) { s += ps[i*CC + c]; q += pq[i*CC + c]; }
    __shared__ float as[2], aq[2];
#pragma unroll
    for (int o = 16; o; o >>= 1) {
        s += __shfl_down_sync(0xffffffffu, s, o);
        q += __shfl_down_sync(0xffffffffu, q, o);
    }
    if ((t & 31) == 0) { as[t >> 5] = s; aq[t >> 5] = q; }
    __syncthreads();
    if (t == 0) {
        s = as[0] + as[1]; q = aq[0] + aq[1];
        float n = (float)(BB*HW);
        float mean = s / n;
        float var  = q / n - mean*mean;
        float scale = gamma[c] * rsqrtf(var + 1e-5f);
        if (which == 0) { g_s1[c] = scale; g_h1[c] = beta[c] - mean*scale; }
        else            { g_s2[c] = scale; g_h2[c] = beta[c] - mean*scale; }
    }
}

// ---------------- conv2: paired-seg mma.sync bf16 2-split GEMM (R14) ----------------
__global__ void __launch_bounds__(256, 2) conv2_mma() {
    extern __shared__ char smraw[];
    C2S2& s = *(C2S2*)smraw;
    const int tid = threadIdx.x, wid = tid >> 5, lid = tid & 31;
    const int t  = blockIdx.x;
    const int pt = t >> 1, coi = t & 1;
    const int b  = pt / 49, pbi = pt % 49;
    const int cob = coi * COT, pb = pbi * PXT;

    s.s1[tid] = g_s1[tid];
    s.h1[tid] = g_h1[tid];
    for (int i = tid; i < NS; i += 256) {
        int k = i / PXT, j = i % PXT;
        int p = pb + j, h = p / WW, w = p % WW;
        int y = h + k/3 - 1, xx = w + k%3 - 1;
        int ok = ((unsigned)y < HH && (unsigned)xx < WW);
        s.ix[i] = ok ? (y*WW + xx) : 0;
        s.vd[i] = ok ? 1.f : 0.f;
    }
    __syncthreads();

    const unsigned uA = smem_u32(&s.Abuf[0][0][0][0]);
    const unsigned uB = smem_u32(&s.Bbuf[0][0][0][0]);
    const int cl  = tid >> 4;
    const int pxg = (tid & 15) * 4;
    const unsigned bswz = SWZ((unsigned)(cl*128 + pxg*2));
    const int aco = tid >> 1, ahalf = tid & 1;
    const unsigned adst = ASWZ((unsigned)(aco*32 + ahalf*16));
    const unsigned aoff = ASWZ((unsigned)((wid*16 + (lid & 15))*32 + (lid >> 4)*16));
    unsigned boff[4];
#pragma unroll
    for (int j = 0; j < 4; j++)
        boff[j] = SWZ((unsigned)((lid & 15)*128 + (j*2 + (lid >> 4))*16));

    float acc[8][4];
#pragma unroll
    for (int j = 0; j < 8; j++)
#pragma unroll
        for (int m = 0; m < 4; m++) acc[j][m] = 0.f;

    const float* tb = g_t1 + (size_t)b*CC*HW;
    float pv[2][4];
    float sc_r[2], sh_r[2];
    int ibr[2];

    auto stage_A2 = [&](int pr, int st) {
#pragma unroll
        for (int sub = 0; sub < 2; sub++) {
            int seg = 2*pr + sub;
            size_t so = ((size_t)seg*CC + cob + aco)*16 + ahalf*8;
            unsigned base = uA + (unsigned)(st*16384 + sub*8192);
            cp16(base         + adst, g_w2bh + so);
            cp16(base + 4096u + adst, g_w2bl + so);
        }
        cp_commit();
    };
    auto fetch2 = [&](int pr) {
#pragma unroll
        for (int sub = 0; sub < 2; sub++) {
            int seg = 2*pr + sub;
            int k = seg >> 4, cb = seg & 15;
            int c = cb*16 + cl;
            ibr[sub] = k*PXT + pxg;
            sc_r[sub] = s.s1[c]; sh_r[sub] = s.h1[c];
            const float* tp = tb + (size_t)c*HW;
#pragma unroll
            for (int j = 0; j < 4; j++) pv[sub][j] = __ldg(tp + s.ix[ibr[sub] + j]);
        }
    };
    auto store_B2 = [&](int st) {
#pragma unroll
        for (int sub = 0; sub < 2; sub++) {
            float w0 = fmaxf(fmaf(pv[sub][0], sc_r[sub], sh_r[sub]), 0.f) * s.vd[ibr[sub]];
            float w1 = fmaxf(fmaf(pv[sub][1], sc_r[sub], sh_r[sub]), 0.f) * s.vd[ibr[sub] + 1];
            float w2 = fmaxf(fmaf(pv[sub][2], sc_r[sub], sh_r[sub]), 0.f) * s.vd[ibr[sub] + 2];
            float w3 = fmaxf(fmaf(pv[sub][3], sc_r[sub], sh_r[sub]), 0.f) * s.vd[ibr[sub] + 3];
            unsigned b0 = __float_as_uint(w0), b1 = __float_as_uint(w1);
            unsigned b2 = __float_as_uint(w2), b3 = __float_as_uint(w3);
            unsigned hA = __byte_perm(b0, b1, 0x7632);
            unsigned hB = __byte_perm(b2, b3, 0x7632);
            float l0 = w0 - __uint_as_float(b0 & 0xFFFF0000u);
            float l1 = w1 - __uint_as_float(b1 & 0xFFFF0000u);
            float l2 = w2 - __uint_as_float(b2 & 0xFFFF0000u);
            float l3 = w3 - __uint_as_float(b3 & 0xFFFF0000u);
            unsigned lA = bf16x2_rn(l1, l0);
            unsigned lB = bf16x2_rn(l3, l2);
            unsigned char* bh = &s.Bbuf[st][sub][0][0];
            unsigned char* bl = &s.Bbuf[st][sub][1][0];
            *(uint2*)(bh + bswz) = make_uint2(hA, hB);
            *(uint2*)(bl + bswz) = make_uint2(lA, lB);
        }
    };

    stage_A2(0, 0);
    fetch2(0);

    for (int pr = 0; pr < NPAIR; pr++) {
        int st = pr & 1;
        cp_wait0();
        store_B2(st);
        __syncthreads();
        if (pr + 1 < NPAIR) { stage_A2(pr + 1, st ^ 1); fetch2(pr + 1); }

#pragma unroll
        for (int sub = 0; sub < 2; sub++) {
            unsigned ab = uA + (unsigned)(st*16384 + sub*8192);
            unsigned bb = uB + (unsigned)(st*8192  + sub*4096);
            uint32_t ah[4], al[4];
            ldsm4(ah, ab         + aoff);
            ldsm4(al, ab + 4096u + aoff);
#pragma unroll
            for (int j = 0; j < 4; j++) {
                uint32_t bh[4], bl[4];
                ldsm4t(bh, bb         + boff[j]);
                ldsm4t(bl, bb + 2048u + boff[j]);
                mma_bf(acc[2*j],     ah, bh[0], bh[1]);
                mma_bf(acc[2*j],     ah, bl[0], bl[1]);
                mma_bf(acc[2*j],     al, bh[0], bh[1]);
                mma_bf(acc[2*j + 1], ah, bh[2], bh[3]);
                mma_bf(acc[2*j + 1], ah, bl[2], bl[3]);
                mma_bf(acc[2*j + 1], al, bh[2], bh[3]);
            }
        }
    }

    {
        int co0 = cob + wid*16 + (lid >> 2);
        int co1 = co0 + 8;
        int pxo = (lid & 3) * 2;
        float* r0 = g_t3 + ((size_t)(b*CC + co0))*HW + pb + pxo;
        float* r1 = g_t3 + ((size_t)(b*CC + co1))*HW + pb + pxo;
        float s0 = 0.f, q0 = 0.f, s1v = 0.f, q1v = 0.f;
#pragma unroll
        for (int j = 0; j < 8; j++) {
            float v0 = acc[j][0], v1 = acc[j][1], v2 = acc[j][2], v3 = acc[j][3];
            r0[j*8]     = v0;  r0[j*8 + 1] = v1;
            r1[j*8]     = v2;  r1[j*8 + 1] = v3;
            s0 += v0 + v1;  q0 += v0*v0 + v1*v1;
            s1v += v2 + v3; q1v += v2*v2 + v3*v3;
        }
#pragma unroll
        for (int o = 1; o <= 2; o <<= 1) {
            s0  += __shfl_xor_sync(0xffffffffu, s0,  o, 4);
            q0  += __shfl_xor_sync(0xffffffffu, q0,  o, 4);
            s1v += __shfl_xor_sync(0xffffffffu, s1v, o, 4);
            q1v += __shfl_xor_sync(0xffffffffu, q1v, o, 4);
        }
        if ((lid & 3) == 0) {
            g_p2s[pt*CC + co0] = s0;   g_p2q[pt*CC + co0] = q0;
            g_p2s[pt*CC + co1] = s1v;  g_p2q[pt*CC + co1] = q1v;
        }
    }
}

// ---------------- epilogue: out = relu(bn2(t3) + x), float4 ----------------
__global__ void epilogue(const float* __restrict__ x, float* __restrict__ out) {
    int i4 = blockIdx.x * blockDim.x + threadIdx.x;
    if (i4 < BB*CC*HW/4) {
        int i = i4 * 4;
        int c = (i / HW) % CC;
        float sc = g_s2[c], sh = g_h2[c];
        float4 t  = *(const float4*)&g_t3[i];
        float4 xv = *(const float4*)&x[i];
        float4 o;
        o.x = fmaxf(fmaf(t.x, sc, sh) + xv.x, 0.f);
        o.y = fmaxf(fmaf(t.y, sc, sh) + xv.y, 0.f);
        o.z = fmaxf(fmaf(t.z, sc, sh) + xv.z, 0.f);
        o.w = fmaxf(fmaf(t.w, sc, sh) + xv.w, 0.f);
        *(float4*)&out[i] = o;
    }
}

// ---------------- launch ----------------
extern "C" void kernel_launch(void* const* d_in, const int* in_sizes, int n_in,
                              void* d_out, int out_size) {
    const float* x      = (const float*)d_in[0];
    const float* w_off  = (const float*)d_in[1];
    const float* b_off  = (const float*)d_in[2];
    const float* w1     = (const float*)d_in[3];
    const float* gamma1 = (const float*)d_in[4];
    const float* beta1  = (const float*)d_in[5];
    const float* w2     = (const float*)d_in[6];
    const float* gamma2 = (const float*)d_in[7];
    const float* beta2  = (const float*)d_in[8];
    float* out = (float*)d_out;

    // idempotent opt-in for >48KB dynamic smem (host API, graph-safe, no alloc)
    cudaFuncSetAttribute(deform_mma, cudaFuncAttributeMaxDynamicSharedMemorySize,
                         (int)sizeof(DS2));
    cudaFuncSetAttribute(conv2_mma, cudaFuncAttributeMaxDynamicSharedMemorySize,
                         (int)sizeof(C2S2));

    prep_w<<<(CK*CC + 255)/256, 256>>>(w1, w2, w_off);
    offset_mma<<<ONT, 256>>>(x);
    deform_mma<<<NTILE, 256, sizeof(DS2)>>>(x, b_off);
    bn_finalize<<<CC, 64>>>(0, gamma1, beta1);
    conv2_mma<<<NTILE, 256, sizeof(C2S2)>>>();
    bn_finalize<<<CC, 64>>>(1, gamma2, beta2);
    epilogue<<<(BB*CC*HW/4 + 255)/256, 256>>>(x, out);
}

// round 17
// speedup vs baseline: 1.1857x; 1.1660x over previous
#include <cuda_runtime.h>
#include <cuda_fp16.h>
#include <cstdint>

#define BB 4
#define CC 256
#define HH 56
#define WW 56
#define HW 3136          // 56*56
#define CK 2304          // C*9
#define COT 128          // co tile
#define PXT 64           // pixel tile (3136 = 49*64)
#define NS  (9*PXT)      // 576 samples per block per channel
#define NTILE (BB*2*49)  // 392 output tiles per GEMM
#define NPB (BB*49)      // partial-stat slots per channel (196)
#define NSEG 144         // K-steps: 9 k-pos x 16 channel-chunks of 16
#define NPAIR 72         // pipeline turns: 2 segs per turn
#define ONT (BB*49)      // offset GEMM tiles (196)

typedef unsigned long long u64;

// ---------------- cp.async helpers ----------------
__device__ __forceinline__ void cp16(unsigned dst, const void* src) {
    asm volatile("cp.async.ca.shared.global [%0], [%1], 16;" :: "r"(dst), "l"(src));
}
__device__ __forceinline__ void cp_commit() { asm volatile("cp.async.commit_group;"); }
__device__ __forceinline__ void cp_wait0()  { asm volatile("cp.async.wait_group 0;"); }

// ---------------- mma.sync / ldmatrix helpers ----------------
__device__ __forceinline__ unsigned smem_u32(const void* p) {
    unsigned a;
    asm("{ .reg .u64 t; cvta.to.shared.u64 t, %1; cvt.u32.u64 %0, t; }" : "=r"(a) : "l"(p));
    return a;
}
__device__ __forceinline__ void ldsm4(uint32_t* r, unsigned a) {
    asm volatile("ldmatrix.sync.aligned.m8n8.x4.shared.b16 {%0,%1,%2,%3}, [%4];"
                 : "=r"(r[0]), "=r"(r[1]), "=r"(r[2]), "=r"(r[3]) : "r"(a));
}
__device__ __forceinline__ void ldsm4t(uint32_t* r, unsigned a) {
    asm volatile("ldmatrix.sync.aligned.m8n8.x4.trans.shared.b16 {%0,%1,%2,%3}, [%4];"
                 : "=r"(r[0]), "=r"(r[1]), "=r"(r[2]), "=r"(r[3]) : "r"(a));
}
__device__ __forceinline__ void mma_fp16(float* d, const uint32_t* a, uint32_t b0, uint32_t b1) {
    asm volatile(
        "mma.sync.aligned.m16n8k16.row.col.f32.f16.f16.f32 "
        "{%0,%1,%2,%3}, {%4,%5,%6,%7}, {%8,%9}, {%0,%1,%2,%3};"
        : "+f"(d[0]), "+f"(d[1]), "+f"(d[2]), "+f"(d[3])
        : "r"(a[0]), "r"(a[1]), "r"(a[2]), "r"(a[3]), "r"(b0), "r"(b1));
}
__device__ __forceinline__ uint32_t f16x2_rn(float hi_src, float lo_src) {
    uint32_t r;
    asm("cvt.rn.f16x2.f32 %0, %1, %2;" : "=r"(r) : "f"(hi_src), "f"(lo_src));
    return r;
}
#define SWZ(o)  ((o) ^ (((o) >> 3) & 0x70))          // SW128 for 128B rows
#define ASWZ(o) ((o) ^ (((o) & 0x80) >> 3))          // conflict-free for 32B rows

// ---------------- scratch (static device memory) ----------------
__device__ float g_offn[BB*18*HW];     // offset conv output (final, single writer)
__device__ float g_t1 [BB*CC*HW];      // deform conv output (pre-BN)
__device__ float g_t3 [BB*CC*HW];      // conv2 output (pre-BN)
__device__ __align__(16) __half g_w1h[NSEG*CC*16];  // w1 fp16 hi: [seg][co][ci]
__device__ __align__(16) __half g_w1l[NSEG*CC*16];  // w1 fp16 lo (22-bit total)
__device__ __align__(16) __half g_w2h[NSEG*CC*16];  // w2 fp16 hi
__device__ __align__(16) __half g_w2l[NSEG*CC*16];  // w2 fp16 lo
__device__ __align__(16) __half g_woh[NSEG*16*64];  // w_off fp16 hi: [seg][ci][co64pad]
__device__ __align__(16) __half g_wol[NSEG*16*64];  // w_off fp16 lo
__device__ float g_s1[CC], g_h1[CC];   // bn1 scale/shift
__device__ float g_s2[CC], g_h2[CC];   // bn2 scale/shift
__device__ float g_p1s[NPB*CC], g_p1q[NPB*CC];   // per-tile bn1 partials
__device__ float g_p2s[NPB*CC], g_p2q[NPB*CC];   // per-tile bn2 partials

// ---------------- prep: fp16 2-term split of w1/w2/w_off ----------------
__global__ void prep_w(const float* __restrict__ w1, const float* __restrict__ w2,
                       const float* __restrict__ w_off) {
    int i = blockIdx.x * blockDim.x + threadIdx.x;
    if (i < CK*CC) {
        int co = i / CK, r = i % CK;
        int c = r / 9, k = r % 9;
        int seg = k*16 + (c >> 4), ci = c & 15;
        size_t o = ((size_t)seg*CC + co)*16 + ci;

        float v = w1[i];
        __half h = __float2half_rn(v);
        g_w1h[o] = h;
        g_w1l[o] = __float2half_rn(v - __half2float(h));

        v = w2[i];
        h = __float2half_rn(v);
        g_w2h[o] = h;
        g_w2l[o] = __float2half_rn(v - __half2float(h));
    }
    if (i < NSEG*16*64) {
        int seg = i >> 10;
        int ci  = (i >> 6) & 15;
        int co  = i & 63;
        int k = seg >> 4, cb = seg & 15;
        int c = cb*16 + ci;
        float v = (co < 18) ? w_off[((size_t)co*CC + c)*9 + k] : 0.f;
        __half h = __float2half_rn(v);
        g_woh[i] = h;
        g_wol[i] = __float2half_rn(v - __half2float(h));
    }
}

// ---------------- offset conv: mma.sync fp16 2-term GEMM ----------------
// 196 CTAs, 256 threads. Tile: 64 px (M) x 32 co (N, 18 live). 72 turns of 2x16 channels.
// A = gathered x (single fp16), B = w_off split (wh, wl).
struct OS {
    int   ix[NS];
    float vd[NS];
    __align__(16) unsigned char Abuf[2][2][2048];      // [stage][sub]: 64px x 16ci fp16
    __align__(16) unsigned char Bbuf[2][2][2][2048];   // [stage][sub][wh/wl]: 16ci x 64co fp16
};

__global__ void __launch_bounds__(256) offset_mma(const float* __restrict__ x) {
    __shared__ OS s;
    const int tid = threadIdx.x, wid = tid >> 5, lid = tid & 31;
    const int t = blockIdx.x;
    const int b = t / 49, pbi = t % 49, pb = pbi * PXT;

    for (int i = tid; i < NS; i += 256) {
        int k = i >> 6, j = i & 63;
        int p = pb + j, hh = p / WW, ww = p % WW;
        int y = hh + (k/3)*2 - 2, xx = ww + (k%3)*2 - 2;
        int ok = ((unsigned)y < HH && (unsigned)xx < WW);
        s.ix[i] = ok ? (y*WW + xx) : 0;
        s.vd[i] = ok ? 1.f : 0.f;
    }
    __syncthreads();

    const unsigned uA = smem_u32(&s.Abuf[0][0][0]);
    const unsigned uB = smem_u32(&s.Bbuf[0][0][0][0]);
    const int apx  = tid >> 2, acig = (tid & 3) * 4;
    const unsigned adst = ASWZ((unsigned)(apx*32 + acig*2));
    const int bhalf = tid >> 7, bci = (tid >> 3) & 15, bch = tid & 7;
    const unsigned bdst = SWZ((unsigned)(bci*128 + bch*16));
    const int pxg = wid >> 1, h = wid & 1;
    const unsigned aoff  = ASWZ((unsigned)((pxg*16 + (lid & 15))*32 + (lid >> 4)*16));
    const unsigned boffh = SWZ((unsigned)((lid & 15)*128 + (h*2 + (lid >> 4))*16));

    float acc[2][4];
#pragma unroll
    for (int nf = 0; nf < 2; nf++)
#pragma unroll
        for (int m = 0; m < 4; m++) acc[nf][m] = 0.f;

    float gv[2][4];
    const float* xb = x + (size_t)b*CC*HW;

    auto stageB = [&](int pr, int st) {
#pragma unroll
        for (int sub = 0; sub < 2; sub++) {
            int seg = 2*pr + sub;
            const __half* src = (bhalf ? g_wol : g_woh) + ((size_t)seg*16 + bci)*64 + bch*8;
            cp16(uB + (unsigned)(st*8192 + sub*4096 + bhalf*2048) + bdst, src);
        }
        cp_commit();
    };
    auto fetchA = [&](int pr) {
#pragma unroll
        for (int sub = 0; sub < 2; sub++) {
            int seg = 2*pr + sub;
            int k = seg >> 4, cb = seg & 15;
            int gi = k*PXT + apx;
            int idx = s.ix[gi];
            float vdv = s.vd[gi];
            const float* xp = xb + ((size_t)(cb*16 + acig))*HW + idx;
#pragma unroll
            for (int j = 0; j < 4; j++) gv[sub][j] = __ldg(xp + (size_t)j*HW) * vdv;
        }
    };
    auto storeA = [&](int st) {
#pragma unroll
        for (int sub = 0; sub < 2; sub++) {
            unsigned hA = f16x2_rn(gv[sub][1], gv[sub][0]);
            unsigned hB = f16x2_rn(gv[sub][3], gv[sub][2]);
            *(uint2*)(&s.Abuf[st][sub][0] + adst) = make_uint2(hA, hB);
        }
    };

    stageB(0, 0);
    fetchA(0);

    for (int pr = 0; pr < NPAIR; pr++) {
        int st = pr & 1;
        cp_wait0();
        storeA(st);
        __syncthreads();
        if (pr + 1 < NPAIR) { stageB(pr + 1, st ^ 1); fetchA(pr + 1); }

#pragma unroll
        for (int sub = 0; sub < 2; sub++) {
            unsigned ab = uA + (unsigned)(st*4096 + sub*2048);
            unsigned bb = uB + (unsigned)(st*8192 + sub*4096);
            uint32_t ah[4];
            ldsm4(ah, ab + aoff);
            uint32_t bh[4], bl[4];
            ldsm4t(bh, bb         + boffh);
            ldsm4t(bl, bb + 2048u + boffh);
            mma_fp16(acc[0], ah, bh[0], bh[1]);
            mma_fp16(acc[0], ah, bl[0], bl[1]);
            mma_fp16(acc[1], ah, bh[2], bh[3]);
            mma_fp16(acc[1], ah, bl[2], bl[3]);
        }
    }

    // epilogue: D[px][co] -> g_offn[b][co][px], co<18 only (single writer)
    {
        int prow = pb + pxg*16 + (lid >> 2);
#pragma unroll
        for (int nf = 0; nf < 2; nf++)
#pragma unroll
            for (int m = 0; m < 4; m++) {
                int co = h*16 + nf*8 + (lid & 3)*2 + (m & 1);
                int pr2 = prow + (m >> 1)*8;
                if (co < 18)
                    g_offn[((size_t)(b*18 + co))*HW + pr2] = acc[nf][m];
            }
    }
}

// ---------------- shared layouts (dynamic smem) ----------------
struct DS2 {   // deform
    int   ix[4][NS];
    float bw[4][NS];
    __align__(16) unsigned char Abuf[2][2][2][4096];   // [stage][sub][wh/wl]: 128co x 16ci fp16
    __align__(16) unsigned char Bbuf[2][2][2048];      // [stage][sub]: 16c x 64px fp16
};
struct C2S2 {  // conv2
    float s1[CC], h1[CC];
    int   ix[NS];
    float vd[NS];
    __align__(16) unsigned char Abuf[2][2][2][4096];
    __align__(16) unsigned char Bbuf[2][2][2048];
};

// ---------------- deformable conv: paired-seg fp16 2-term GEMM ----------------
__global__ void __launch_bounds__(256, 2) deform_mma(const float* __restrict__ x,
                                                     const float* __restrict__ b_off) {
    extern __shared__ char smraw[];
    DS2& s = *(DS2*)smraw;
    const int tid = threadIdx.x, wid = tid >> 5, lid = tid & 31;
    const int t  = blockIdx.x;
    const int pt = t >> 1, coi = t & 1;
    const int b  = pt / 49, pbi = pt % 49;
    const int cob = coi * COT, pb = pbi * PXT;

    for (int i = tid; i < NS; i += 256) {
        int k = i / PXT, j = i % PXT;
        int p = pb + j, h = p / WW, w = p % WW;
        float dy = g_offn[(size_t)(b*18 + 2*k    )*HW + p] + b_off[2*k];
        float dx = g_offn[(size_t)(b*18 + 2*k + 1)*HW + p] + b_off[2*k + 1];
        float py = (float)(h + (k/3)*2 - 2) + dy;
        float px = (float)(w + (k%3)*2 - 2) + dx;
        float y0f = floorf(py), x0f = floorf(px);
        float wy = py - y0f, wx = px - x0f;
        int yi = (int)y0f, xi = (int)x0f;
        float vy0 = ((unsigned)yi      < HH) ? 1.f : 0.f;
        float vy1 = ((unsigned)(yi+1)  < HH) ? 1.f : 0.f;
        float vx0 = ((unsigned)xi      < WW) ? 1.f : 0.f;
        float vx1 = ((unsigned)(xi+1)  < WW) ? 1.f : 0.f;
        int cy0 = min(max(yi,   0), HH-1), cy1 = min(max(yi+1, 0), HH-1);
        int cx0 = min(max(xi,   0), WW-1), cx1 = min(max(xi+1, 0), WW-1);
        s.ix[0][i] = cy0*WW + cx0;  s.ix[1][i] = cy0*WW + cx1;
        s.ix[2][i] = cy1*WW + cx0;  s.ix[3][i] = cy1*WW + cx1;
        s.bw[0][i] = (1.f-wy)*(1.f-wx)*vy0*vx0;
        s.bw[1][i] = (1.f-wy)*wx      *vy0*vx1;
        s.bw[2][i] = wy*(1.f-wx)      *vy1*vx0;
        s.bw[3][i] = wy*wx            *vy1*vx1;
    }
    __syncthreads();

    const unsigned uA = smem_u32(&s.Abuf[0][0][0][0]);
    const unsigned uB = smem_u32(&s.Bbuf[0][0][0]);
    const int cl  = tid >> 4;
    const int pxg = (tid & 15) * 4;
    const unsigned bswz = SWZ((unsigned)(cl*128 + pxg*2));
    const int aco = tid >> 1, ahalf = tid & 1;
    const unsigned adst = ASWZ((unsigned)(aco*32 + ahalf*16));
    const unsigned aoff = ASWZ((unsigned)((wid*16 + (lid & 15))*32 + (lid >> 4)*16));
    unsigned boff[4];
#pragma unroll
    for (int j = 0; j < 4; j++)
        boff[j] = SWZ((unsigned)((lid & 15)*128 + (j*2 + (lid >> 4))*16));

    float acc[8][4];
#pragma unroll
    for (int j = 0; j < 8; j++)
#pragma unroll
        for (int m = 0; m < 4; m++) acc[j][m] = 0.f;

    const float* xb = x + (size_t)b*CC*HW;
    float pv[2][4][4];
    int ibr[2];

    auto stage_A2 = [&](int pr, int st) {
#pragma unroll
        for (int sub = 0; sub < 2; sub++) {
            int seg = 2*pr + sub;
            size_t so = ((size_t)seg*CC + cob + aco)*16 + ahalf*8;
            unsigned base = uA + (unsigned)(st*16384 + sub*8192);
            cp16(base         + adst, g_w1h + so);
            cp16(base + 4096u + adst, g_w1l + so);
        }
        cp_commit();
    };
    auto fetch2 = [&](int pr) {
#pragma unroll
        for (int sub = 0; sub < 2; sub++) {
            int seg = 2*pr + sub;
            int k = seg >> 4, cb = seg & 15;
            int c = cb*16 + cl;
            ibr[sub] = k*PXT + pxg;
            const float* xp = xb + (size_t)c*HW;
#pragma unroll
            for (int j = 0; j < 4; j++) {
                int i = ibr[sub] + j;
                pv[sub][j][0] = __ldg(xp + s.ix[0][i]);
                pv[sub][j][1] = __ldg(xp + s.ix[1][i]);
                pv[sub][j][2] = __ldg(xp + s.ix[2][i]);
                pv[sub][j][3] = __ldg(xp + s.ix[3][i]);
            }
        }
    };
    auto store_B2 = [&](int st) {
#pragma unroll
        for (int sub = 0; sub < 2; sub++) {
            float wv[4];
#pragma unroll
            for (int j = 0; j < 4; j++) {
                int i = ibr[sub] + j;
                wv[j] = pv[sub][j][0]*s.bw[0][i] + pv[sub][j][1]*s.bw[1][i]
                      + pv[sub][j][2]*s.bw[2][i] + pv[sub][j][3]*s.bw[3][i];
            }
            unsigned hA = f16x2_rn(wv[1], wv[0]);
            unsigned hB = f16x2_rn(wv[3], wv[2]);
            *(uint2*)(&s.Bbuf[st][sub][0] + bswz) = make_uint2(hA, hB);
        }
    };

    stage_A2(0, 0);
    fetch2(0);

    for (int pr = 0; pr < NPAIR; pr++) {
        int st = pr & 1;
        cp_wait0();
        store_B2(st);
        __syncthreads();
        if (pr + 1 < NPAIR) { stage_A2(pr + 1, st ^ 1); fetch2(pr + 1); }

#pragma unroll
        for (int sub = 0; sub < 2; sub++) {
            unsigned ab = uA + (unsigned)(st*16384 + sub*8192);
            unsigned bb = uB + (unsigned)(st*4096  + sub*2048);
            uint32_t ah[4], al[4];
            ldsm4(ah, ab         + aoff);
            ldsm4(al, ab + 4096u + aoff);
#pragma unroll
            for (int j = 0; j < 4; j++) {
                uint32_t bh[4];
                ldsm4t(bh, bb + boff[j]);
                mma_fp16(acc[2*j],     ah, bh[0], bh[1]);
                mma_fp16(acc[2*j],     al, bh[0], bh[1]);
                mma_fp16(acc[2*j + 1], ah, bh[2], bh[3]);
                mma_fp16(acc[2*j + 1], al, bh[2], bh[3]);
            }
        }
    }

    {
        int co0 = cob + wid*16 + (lid >> 2);
        int co1 = co0 + 8;
        int pxo = (lid & 3) * 2;
        float* r0 = g_t1 + ((size_t)(b*CC + co0))*HW + pb + pxo;
        float* r1 = g_t1 + ((size_t)(b*CC + co1))*HW + pb + pxo;
        float s0 = 0.f, q0 = 0.f, s1v = 0.f, q1v = 0.f;
#pragma unroll
        for (int j = 0; j < 8; j++) {
            float v0 = acc[j][0], v1 = acc[j][1], v2 = acc[j][2], v3 = acc[j][3];
            r0[j*8]     = v0;  r0[j*8 + 1] = v1;
            r1[j*8]     = v2;  r1[j*8 + 1] = v3;
            s0 += v0 + v1;  q0 += v0*v0 + v1*v1;
            s1v += v2 + v3; q1v += v2*v2 + v3*v3;
        }
#pragma unroll
        for (int o = 1; o <= 2; o <<= 1) {
            s0  += __shfl_xor_sync(0xffffffffu, s0,  o, 4);
            q0  += __shfl_xor_sync(0xffffffffu, q0,  o, 4);
            s1v += __shfl_xor_sync(0xffffffffu, s1v, o, 4);
            q1v += __shfl_xor_sync(0xffffffffu, q1v, o, 4);
        }
        if ((lid & 3) == 0) {
            g_p1s[pt*CC + co0] = s0;   g_p1q[pt*CC + co0] = q0;
            g_p1s[pt*CC + co1] = s1v;  g_p1q[pt*CC + co1] = q1v;
        }
    }
}

// ---------------- BN finalize ----------------
__global__ void bn_finalize(int which, const float* __restrict__ gamma,
                            const float* __restrict__ beta) {
    int c = blockIdx.x, t = threadIdx.x;
    const float* ps = (which == 0) ? g_p1s : g_p2s;
    const float* pq = (which == 0) ? g_p1q : g_p2q;
    float s = 0.f, q = 0.f;
    for (int i = t; i < NPB; i += 64) { s += ps[i*CC + c]; q += pq[i*CC + c]; }
    __shared__ float as[2], aq[2];
#pragma unroll
    for (int o = 16; o; o >>= 1) {
        s += __shfl_down_sync(0xffffffffu, s, o);
        q += __shfl_down_sync(0xffffffffu, q, o);
    }
    if ((t & 31) == 0) { as[t >> 5] = s; aq[t >> 5] = q; }
    __syncthreads();
    if (t == 0) {
        s = as[0] + as[1]; q = aq[0] + aq[1];
        float n = (float)(BB*HW);
        float mean = s / n;
        float var  = q / n - mean*mean;
        float scale = gamma[c] * rsqrtf(var + 1e-5f);
        if (which == 0) { g_s1[c] = scale; g_h1[c] = beta[c] - mean*scale; }
        else            { g_s2[c] = scale; g_h2[c] = beta[c] - mean*scale; }
    }
}

// ---------------- conv2: paired-seg fp16 2-term GEMM ----------------
__global__ void __launch_bounds__(256, 2) conv2_mma() {
    extern __shared__ char smraw[];
    C2S2& s = *(C2S2*)smraw;
    const int tid = threadIdx.x, wid = tid >> 5, lid = tid & 31;
    const int t  = blockIdx.x;
    const int pt = t >> 1, coi = t & 1;
    const int b  = pt / 49, pbi = pt % 49;
    const int cob = coi * COT, pb = pbi * PXT;

    s.s1[tid] = g_s1[tid];
    s.h1[tid] = g_h1[tid];
    for (int i = tid; i < NS; i += 256) {
        int k = i / PXT, j = i % PXT;
        int p = pb + j, h = p / WW, w = p % WW;
        int y = h + k/3 - 1, xx = w + k%3 - 1;
        int ok = ((unsigned)y < HH && (unsigned)xx < WW);
        s.ix[i] = ok ? (y*WW + xx) : 0;
        s.vd[i] = ok ? 1.f : 0.f;
    }
    __syncthreads();

    const unsigned uA = smem_u32(&s.Abuf[0][0][0][0]);
    const unsigned uB = smem_u32(&s.Bbuf[0][0][0]);
    const int cl  = tid >> 4;
    const int pxg = (tid & 15) * 4;
    const unsigned bswz = SWZ((unsigned)(cl*128 + pxg*2));
    const int aco = tid >> 1, ahalf = tid & 1;
    const unsigned adst = ASWZ((unsigned)(aco*32 + ahalf*16));
    const unsigned aoff = ASWZ((unsigned)((wid*16 + (lid & 15))*32 + (lid >> 4)*16));
    unsigned boff[4];
#pragma unroll
    for (int j = 0; j < 4; j++)
        boff[j] = SWZ((unsigned)((lid & 15)*128 + (j*2 + (lid >> 4))*16));

    float acc[8][4];
#pragma unroll
    for (int j = 0; j < 8; j++)
#pragma unroll
        for (int m = 0; m < 4; m++) acc[j][m] = 0.f;

    const float* tb = g_t1 + (size_t)b*CC*HW;
    float pv[2][4];
    float sc_r[2], sh_r[2];
    int ibr[2];

    auto stage_A2 = [&](int pr, int st) {
#pragma unroll
        for (int sub = 0; sub < 2; sub++) {
            int seg = 2*pr + sub;
            size_t so = ((size_t)seg*CC + cob + aco)*16 + ahalf*8;
            unsigned base = uA + (unsigned)(st*16384 + sub*8192);
            cp16(base         + adst, g_w2h + so);
            cp16(base + 4096u + adst, g_w2l + so);
        }
        cp_commit();
    };
    auto fetch2 = [&](int pr) {
#pragma unroll
        for (int sub = 0; sub < 2; sub++) {
            int seg = 2*pr + sub;
            int k = seg >> 4, cb = seg & 15;
            int c = cb*16 + cl;
            ibr[sub] = k*PXT + pxg;
            sc_r[sub] = s.s1[c]; sh_r[sub] = s.h1[c];
            const float* tp = tb + (size_t)c*HW;
#pragma unroll
            for (int j = 0; j < 4; j++) pv[sub][j] = __ldg(tp + s.ix[ibr[sub] + j]);
        }
    };
    auto store_B2 = [&](int st) {
#pragma unroll
        for (int sub = 0; sub < 2; sub++) {
            float w0 = fmaxf(fmaf(pv[sub][0], sc_r[sub], sh_r[sub]), 0.f) * s.vd[ibr[sub]];
            float w1 = fmaxf(fmaf(pv[sub][1], sc_r[sub], sh_r[sub]), 0.f) * s.vd[ibr[sub] + 1];
            float w2 = fmaxf(fmaf(pv[sub][2], sc_r[sub], sh_r[sub]), 0.f) * s.vd[ibr[sub] + 2];
            float w3 = fmaxf(fmaf(pv[sub][3], sc_r[sub], sh_r[sub]), 0.f) * s.vd[ibr[sub] + 3];
            unsigned hA = f16x2_rn(w1, w0);
            unsigned hB = f16x2_rn(w3, w2);
            *(uint2*)(&s.Bbuf[st][sub][0] + bswz) = make_uint2(hA, hB);
        }
    };

    stage_A2(0, 0);
    fetch2(0);

    for (int pr = 0; pr < NPAIR; pr++) {
        int st = pr & 1;
        cp_wait0();
        store_B2(st);
        __syncthreads();
        if (pr + 1 < NPAIR) { stage_A2(pr + 1, st ^ 1); fetch2(pr + 1); }

#pragma unroll
        for (int sub = 0; sub < 2; sub++) {
            unsigned ab = uA + (unsigned)(st*16384 + sub*8192);
            unsigned bb = uB + (unsigned)(st*4096  + sub*2048);
            uint32_t ah[4], al[4];
            ldsm4(ah, ab         + aoff);
            ldsm4(al, ab + 4096u + aoff);
#pragma unroll
            for (int j = 0; j < 4; j++) {
                uint32_t bh[4];
                ldsm4t(bh, bb + boff[j]);
                mma_fp16(acc[2*j],     ah, bh[0], bh[1]);
                mma_fp16(acc[2*j],     al, bh[0], bh[1]);
                mma_fp16(acc[2*j + 1], ah, bh[2], bh[3]);
                mma_fp16(acc[2*j + 1], al, bh[2], bh[3]);
            }
        }
    }

    {
        int co0 = cob + wid*16 + (lid >> 2);
        int co1 = co0 + 8;
        int pxo = (lid & 3) * 2;
        float* r0 = g_t3 + ((size_t)(b*CC + co0))*HW + pb + pxo;
        float* r1 = g_t3 + ((size_t)(b*CC + co1))*HW + pb + pxo;
        float s0 = 0.f, q0 = 0.f, s1v = 0.f, q1v = 0.f;
#pragma unroll
        for (int j = 0; j < 8; j++) {
            float v0 = acc[j][0], v1 = acc[j][1], v2 = acc[j][2], v3 = acc[j][3];
            r0[j*8]     = v0;  r0[j*8 + 1] = v1;
            r1[j*8]     = v2;  r1[j*8 + 1] = v3;
            s0 += v0 + v1;  q0 += v0*v0 + v1*v1;
            s1v += v2 + v3; q1v += v2*v2 + v3*v3;
        }
#pragma unroll
        for (int o = 1; o <= 2; o <<= 1) {
            s0  += __shfl_xor_sync(0xffffffffu, s0,  o, 4);
            q0  += __shfl_xor_sync(0xffffffffu, q0,  o, 4);
            s1v += __shfl_xor_sync(0xffffffffu, s1v, o, 4);
            q1v += __shfl_xor_sync(0xffffffffu, q1v, o, 4);
        }
        if ((lid & 3) == 0) {
            g_p2s[pt*CC + co0] = s0;   g_p2q[pt*CC + co0] = q0;
            g_p2s[pt*CC + co1] = s1v;  g_p2q[pt*CC + co1] = q1v;
        }
    }
}

// ---------------- epilogue: out = relu(bn2(t3) + x), float4 ----------------
__global__ void epilogue(const float* __restrict__ x, float* __restrict__ out) {
    int i4 = blockIdx.x * blockDim.x + threadIdx.x;
    if (i4 < BB*CC*HW/4) {
        int i = i4 * 4;
        int c = (i / HW) % CC;
        float sc = g_s2[c], sh = g_h2[c];
        float4 t  = *(const float4*)&g_t3[i];
        float4 xv = *(const float4*)&x[i];
        float4 o;
        o.x = fmaxf(fmaf(t.x, sc, sh) + xv.x, 0.f);
        o.y = fmaxf(fmaf(t.y, sc, sh) + xv.y, 0.f);
        o.z = fmaxf(fmaf(t.z, sc, sh) + xv.z, 0.f);
        o.w = fmaxf(fmaf(t.w, sc, sh) + xv.w, 0.f);
        *(float4*)&out[i] = o;
    }
}

// ---------------- launch ----------------
extern "C" void kernel_launch(void* const* d_in, const int* in_sizes, int n_in,
                              void* d_out, int out_size) {
    const float* x      = (const float*)d_in[0];
    const float* w_off  = (const float*)d_in[1];
    const float* b_off  = (const float*)d_in[2];
    const float* w1     = (const float*)d_in[3];
    const float* gamma1 = (const float*)d_in[4];
    const float* beta1  = (const float*)d_in[5];
    const float* w2     = (const float*)d_in[6];
    const float* gamma2 = (const float*)d_in[7];
    const float* beta2  = (const float*)d_in[8];
    float* out = (float*)d_out;

    cudaFuncSetAttribute(deform_mma, cudaFuncAttributeMaxDynamicSharedMemorySize,
                         (int)sizeof(DS2));
    cudaFuncSetAttribute(conv2_mma, cudaFuncAttributeMaxDynamicSharedMemorySize,
                         (int)sizeof(C2S2));

    prep_w<<<(CK*CC + 255)/256, 256>>>(w1, w2, w_off);
    offset_mma<<<ONT, 256>>>(x);
    deform_mma<<<NTILE, 256, sizeof(DS2)>>>(x, b_off);
    bn_finalize<<<CC, 64>>>(0, gamma1, beta1);
    conv2_mma<<<NTILE, 256, sizeof(C2S2)>>>();
    bn_finalize<<<CC, 64>>>(1, gamma2, beta2);
    epilogue<<<(BB*CC*HW/4 + 255)/256, 256>>>(x, out);
}